// round 7
// baseline (speedup 1.0000x reference)
#include <cuda_runtime.h>

#define NS   128
#define NT   2048
#define NB   64
#define NTHR 640   // 128 g0 (matvec+combine) + 512 dur (4 slices x 128 states)

// float-index offsets in dynamic smem
#define OFF_EA    0        // 16384: swizzled transposed exp(A)
#define OFF_RV    16384    // 16384: ring values          [slot][j]
#define OFF_RR    32768    // 16384: ring ref-at-insert   [slot][j]
#define OFF_PSH   49152    // 256:  [buf][j]  exp(alpha - M), double-buffered by parity
#define OFF_PDUR  49408    // 1024: [buf][4*j+s]
#define OFF_FLAG  50432    // 256:  [buf][j] rescale factor
#define OFF_REFS  50688    // 256:  [buf][j] ref after that step
#define OFF_ED    50944    // 256:  [j*2+{0,1}] = exp(D[j][0..1])
#define OFF_WRED  51200    // 8:    [buf][w] per-warp alpha maxes, double-buffered
#define OFF_EFLG  51208    // 2 ints: emergency-rescale generation, by parity
#define OFF_FIN   51212    // 16
#define SMEM_FLOATS 51232  // ~200.1 KB

typedef unsigned long long u64;

__device__ __forceinline__ u64 pk2(float lo, float hi) {
    u64 r;
    asm("mov.b64 %0, {%1, %2};" : "=l"(r)
        : "r"(__float_as_uint(lo)), "r"(__float_as_uint(hi)));
    return r;
}
__device__ __forceinline__ void upk2(u64 v, float& lo, float& hi) {
    unsigned a, b;
    asm("mov.b64 {%0, %1}, %2;" : "=r"(a), "=r"(b) : "l"(v));
    lo = __uint_as_float(a); hi = __uint_as_float(b);
}
__device__ __forceinline__ float lo2(u64 v) { float a, b; upk2(v, a, b); return a; }
__device__ __forceinline__ u64 ffma2(u64 a, u64 b, u64 c) {
    u64 d;
    asm("fma.rn.f32x2 %0, %1, %2, %3;" : "=l"(d) : "l"(a), "l"(b), "l"(c));
    return d;
}
__device__ __forceinline__ u64 fmul2(u64 a, u64 b) {
    u64 d;
    asm("mul.rn.f32x2 %0, %1, %2;" : "=l"(d) : "l"(a), "l"(b));
    return d;
}
__device__ __forceinline__ unsigned f2key(float x) {
    int i = __float_as_int(x);
    return (unsigned)(i ^ ((i >> 31) | 0x80000000));
}
__device__ __forceinline__ float key2f(unsigned k) {
    int i = ((int)k < 0) ? (int)(k ^ 0x80000000u) : (int)(~k);
    return __int_as_float(i);
}

__global__ __launch_bounds__(NTHR, 1)
void hsmm_fwd_kernel(const float* __restrict__ logB,
                     const float* __restrict__ pi,
                     const float* __restrict__ A,
                     const float* __restrict__ D,
                     float* __restrict__ out)
{
    extern __shared__ float sm[];
    float* ring_v = sm + OFF_RV;
    float* ring_r = sm + OFF_RR;
    float* p_sh   = sm + OFF_PSH;
    float* pdur   = sm + OFF_PDUR;
    float* flagS  = sm + OFF_FLAG;
    float* refsS  = sm + OFF_REFS;
    float* eD01   = sm + OFF_ED;
    float* wred   = sm + OFF_WRED;
    int*   eflg   = (int*)(sm + OFF_EFLG);
    float* fin    = sm + OFF_FIN;

    const int tid  = threadIdx.x;
    const int b    = blockIdx.x;
    const int lane = tid & 31;
    const int w    = tid >> 5;
    const int j    = tid & 127;

    // ---------- init smem ----------
    for (int lin = tid; lin < 16384; lin += NTHR) {
        int jj = lin >> 7, ii = lin & 127;
        int dst = (jj << 7) + ((((ii >> 2) ^ (jj & 31)) << 2)) + (ii & 3);
        sm[OFF_EA + dst] = __expf(A[ii * NS + jj]);
        ring_v[lin] = 0.0f;
        ring_r[lin] = 0.0f;
    }
    for (int lin = tid; lin < 1024; lin += NTHR) pdur[lin] = 0.0f;
    if (tid < 128) {
        p_sh[tid] = 0.0f;  p_sh[128 + tid] = 0.0f;
        flagS[tid] = 1.0f; flagS[128 + tid] = 1.0f;
        refsS[tid] = 0.0f; refsS[128 + tid] = 0.0f;
        eD01[2 * tid]     = __expf(D[tid * NS + 0]);
        eD01[2 * tid + 1] = __expf(D[tid * NS + 1]);
    }
    if (tid < 8) wred[tid] = 0.0f;
    if (tid < 2) eflg[tid] = -7;

    // ---------- role setup ----------
    float alpha = 0.f, cum = 0.f, ref = 0.f, v_prev = 0.f, fpend = 1.f, Mprev = 0.f;
    float lb_cur = 0.f, pij = 0.f;
    const float* lbp = logB + (size_t)b * NT * NS + j;
    if (tid < 128) { lb_cur = lbp[0]; pij = pi[j]; }

    u64 wt2[16], q2[16];
    int s = 0;
    if (tid >= 128) {
        s = (tid - 128) >> 7;                       // duration slice 0..3
        #pragma unroll
        for (int k = 0; k < 16; ++k) {
            int cA = 2 + 32 * s + k;                // tap d-1 = 2+32s+k
            int cB = cA + 16;
            float wa = (cA < 128) ? __expf(D[j * NS + cA]) : 0.0f;
            float wb = (cB < 128) ? __expf(D[j * NS + cB]) : 0.0f;
            wt2[k] = pk2(wa, wb);
            q2[k]  = 0ull;
        }
    }
    __syncthreads();

    const u64 Z = 0ull;
    for (int t = 0; t < NT; ++t) {
        if (tid < 128) {
            // ================= g0: full matvec + combine, one thread per state =================
            float4 pd4 = *(const float4*)(pdur + (t & 1) * 512 + 4 * j);
            float2 e01 = *(const float2*)(eD01 + 2 * j);
            float4 wr4 = *(const float4*)(wred + (t & 1) * 4);   // warp maxes of alpha_{t-1}

            float v;
            if (t == 0) {
                v = __expf(pij);
            } else {
                const float* eAj = sm + OFF_EA + (j << 7);
                const float* psc = p_sh + (t & 1) * 128;
                const unsigned sw = (unsigned)(j & 31);
                u64 a0 = Z, a1 = Z, a2 = Z, a3 = Z;
                #pragma unroll 8
                for (int c = 0; c < 32; ++c) {
                    ulonglong2 ev = *(const ulonglong2*)(eAj + (((unsigned)c ^ sw) << 2));
                    ulonglong2 pv = *(const ulonglong2*)(psc + (c << 2));
                    if (c & 1) { a2 = ffma2(pv.x, ev.x, a2); a3 = ffma2(pv.y, ev.y, a3); }
                    else       { a0 = ffma2(pv.x, ev.x, a0); a1 = ffma2(pv.y, ev.y, a1); }
                }
                float x0, x1, y0, y1, z0, z1, u0, u1;
                upk2(a0, x0, x1); upk2(a1, y0, y1); upk2(a2, z0, z1); upk2(a3, u0, u1);
                float S = ((x0 + x1) + (y0 + y1)) + ((z0 + z1) + (u0 + u1));
                v = S * __expf(Mprev - cum - ref);  // exp(entry_t - cum_t - ref)
            }
            float tail = (pd4.x + pd4.y) + (pd4.z + pd4.w);
            float dot = fmaf(fpend, tail, fmaf(e01.y, v_prev, e01.x * v));

            cum += lb_cur;                          // cum[t+1]
            alpha = cum + ref + __logf(dot);
            lb_cur = (t + 1 < NT) ? lbp[(size_t)(t + 1) * NS] : 0.0f;

            bool sched = ((t & 15) == 15);
            bool emerg = (v > 1e13f);
            float ins, fac;
            if (emerg | (sched & (v > 1e-35f))) {
                float lv = __logf(v);
                ref += lv; ins = 1.0f; fac = __expf(-lv);
                if (emerg & !sched) eflg[t & 1] = t;   // benign same-value race
            } else { ins = v; fac = 1.0f; }
            fpend = fac; v_prev = ins;
            flagS[(t & 1) * 128 + j] = fac;
            refsS[(t & 1) * 128 + j] = ref;
            const int sl = t & 127;
            ring_v[sl * NS + j] = ins;
            ring_r[sl * NS + j] = ref;

            float Mnow = fmaxf(fmaxf(wr4.x, wr4.y), fmaxf(wr4.z, wr4.w));
            p_sh[((t + 1) & 1) * 128 + j] = __expf(alpha - Mnow);
            Mprev = Mnow;

            unsigned ku = f2key(alpha), r;
            asm volatile("redux.sync.max.u32 %0, %1, 0xffffffff;" : "=r"(r) : "r"(ku));
            if (lane == 0) wred[((t + 1) & 1) * 4 + w] = key2f(r);
        } else {
            // ================= dur: 32-tap sliding window in registers =================
            if (t > 0) {
                bool rs = ((((t - 1) & 15) == 15) || (eflg[(t - 1) & 1] == t - 1));
                if (rs) {
                    float fac = flagS[((t - 1) & 1) * 128 + j];
                    u64 fac2 = pk2(fac, fac);
                    #pragma unroll
                    for (int k = 0; k < 16; ++k) q2[k] = fmul2(q2[k], fac2);
                }
            }
            const int bslot = (t - 1 - 32 * s) & 127;     // v_{t-1-32s}  (fixed off-by-one)
            float bv = ring_v[bslot * NS + j];
            float br = ring_r[bslot * NS + j];
            float rn = refsS[((t - 1) & 1) * 128 + j];
            float nv = __expf(fminf(__logf(bv) + (br - rn), 85.0f));
            float lo15 = lo2(q2[15]);
            #pragma unroll
            for (int k = 15; k >= 1; --k) q2[k] = q2[k - 1];
            q2[0] = pk2(nv, lo15);

            u64 a0 = Z, a1 = Z, a2 = Z, a3 = Z;
            #pragma unroll
            for (int k = 0; k < 16; k += 4) {
                a0 = ffma2(q2[k + 0], wt2[k + 0], a0);
                a1 = ffma2(q2[k + 1], wt2[k + 1], a1);
                a2 = ffma2(q2[k + 2], wt2[k + 2], a2);
                a3 = ffma2(q2[k + 3], wt2[k + 3], a3);
            }
            float x0, x1, y0, y1, z0, z1, u0, u1;
            upk2(a0, x0, x1); upk2(a1, y0, y1); upk2(a2, z0, z1); upk2(a3, u0, u1);
            pdur[((t + 1) & 1) * 512 + 4 * j + s] =
                ((x0 + x1) + (y0 + y1)) + ((z0 + z1) + (u0 + u1));
        }
        __syncthreads();   // loop carry
    }

    // ---------- loglik[b] = LSE_j alpha[T-1, j] ----------
    if (tid < 128) {
        float mv = alpha;
        #pragma unroll
        for (int o = 16; o > 0; o >>= 1)
            mv = fmaxf(mv, __shfl_xor_sync(0xffffffffu, mv, o));
        if (lane == 0) fin[w] = mv;
    }
    __syncthreads();
    float m = fmaxf(fmaxf(fin[0], fin[1]), fmaxf(fin[2], fin[3]));
    if (tid < 128) {
        float e = __expf(alpha - m);
        #pragma unroll
        for (int o = 16; o > 0; o >>= 1)
            e += __shfl_xor_sync(0xffffffffu, e, o);
        if (lane == 0) fin[8 + w] = e;
    }
    __syncthreads();
    if (tid == 0) {
        float ssum = (fin[8] + fin[9]) + (fin[10] + fin[11]);
        out[b] = m + __logf(ssum);
    }
}

extern "C" void kernel_launch(void* const* d_in, const int* in_sizes, int n_in,
                              void* d_out, int out_size)
{
    const float* logB = (const float*)d_in[0];
    const float* pi   = (const float*)d_in[1];
    const float* A    = (const float*)d_in[2];
    const float* D    = (const float*)d_in[3];
    float* out = (float*)d_out;

    const size_t smem_bytes = (size_t)SMEM_FLOATS * sizeof(float);  // ~200.1 KB
    cudaFuncSetAttribute(hsmm_fwd_kernel,
                         cudaFuncAttributeMaxDynamicSharedMemorySize,
                         (int)smem_bytes);
    hsmm_fwd_kernel<<<NB, NTHR, smem_bytes>>>(logB, pi, A, D, out);
}

// round 8
// speedup vs baseline: 1.0010x; 1.0010x over previous
#include <cuda_runtime.h>

#define NS   128
#define NT   2048
#define NB   64
#define NTHR 640   // 128 g0 (matvec+combine) + 512 dur (4 slices x 128 states)

// float-index offsets in dynamic smem
#define OFF_EA    0        // 16384: swizzled transposed exp(A)
#define OFF_RV    16384    // 16384: ring values          [slot][j]
#define OFF_RR    32768    // 16384: ring ref-at-insert   [slot][j]
#define OFF_PSH   49152    // 256:  [buf][j]  exp(alpha - M), double-buffered by parity
#define OFF_PDUR  49408    // 1024: [buf][4*j+s]
#define OFF_FLAG  50432    // 256:  [buf][j] rescale factor
#define OFF_REFS  50688    // 256:  [buf][j] ref after that step
#define OFF_ED    50944    // 256:  [j*2+{0,1}] = exp(D[j][0..1])
#define OFF_WRED  51200    // 8:    [buf][w] per-warp alpha maxes, double-buffered
#define OFF_EFLG  51208    // 2 ints: emergency-rescale generation, by parity
#define OFF_FIN   51212    // 16
#define SMEM_FLOATS 51232  // ~200.1 KB

typedef unsigned long long u64;

__device__ __forceinline__ u64 pk2(float lo, float hi) {
    u64 r;
    asm("mov.b64 %0, {%1, %2};" : "=l"(r)
        : "r"(__float_as_uint(lo)), "r"(__float_as_uint(hi)));
    return r;
}
__device__ __forceinline__ void upk2(u64 v, float& lo, float& hi) {
    unsigned a, b;
    asm("mov.b64 {%0, %1}, %2;" : "=r"(a), "=r"(b) : "l"(v));
    lo = __uint_as_float(a); hi = __uint_as_float(b);
}
__device__ __forceinline__ float lo2(u64 v) { float a, b; upk2(v, a, b); return a; }
__device__ __forceinline__ u64 ffma2(u64 a, u64 b, u64 c) {
    u64 d;
    asm("fma.rn.f32x2 %0, %1, %2, %3;" : "=l"(d) : "l"(a), "l"(b), "l"(c));
    return d;
}
__device__ __forceinline__ u64 fmul2(u64 a, u64 b) {
    u64 d;
    asm("mul.rn.f32x2 %0, %1, %2;" : "=l"(d) : "l"(a), "l"(b));
    return d;
}
__device__ __forceinline__ unsigned f2key(float x) {
    int i = __float_as_int(x);
    return (unsigned)(i ^ ((i >> 31) | 0x80000000));
}
__device__ __forceinline__ float key2f(unsigned k) {
    int i = ((int)k < 0) ? (int)(k ^ 0x80000000u) : (int)(~k);
    return __int_as_float(i);
}

__global__ __launch_bounds__(NTHR, 1)
void hsmm_fwd_kernel(const float* __restrict__ logB,
                     const float* __restrict__ pi,
                     const float* __restrict__ A,
                     const float* __restrict__ D,
                     float* __restrict__ out)
{
    extern __shared__ float sm[];
    float* ring_v = sm + OFF_RV;
    float* ring_r = sm + OFF_RR;
    float* p_sh   = sm + OFF_PSH;
    float* pdur   = sm + OFF_PDUR;
    float* flagS  = sm + OFF_FLAG;
    float* refsS  = sm + OFF_REFS;
    float* eD01   = sm + OFF_ED;
    float* wred   = sm + OFF_WRED;
    int*   eflg   = (int*)(sm + OFF_EFLG);
    float* fin    = sm + OFF_FIN;

    const int tid  = threadIdx.x;
    const int b    = blockIdx.x;
    const int lane = tid & 31;
    const int w    = tid >> 5;
    const int j    = tid & 127;

    // ---------- init smem ----------
    for (int lin = tid; lin < 16384; lin += NTHR) {
        int jj = lin >> 7, ii = lin & 127;
        int dst = (jj << 7) + ((((ii >> 2) ^ (jj & 31)) << 2)) + (ii & 3);
        sm[OFF_EA + dst] = __expf(A[ii * NS + jj]);
        ring_v[lin] = 0.0f;
        ring_r[lin] = 0.0f;
    }
    for (int lin = tid; lin < 1024; lin += NTHR) pdur[lin] = 0.0f;
    if (tid < 128) {
        p_sh[tid] = 0.0f;  p_sh[128 + tid] = 0.0f;
        flagS[tid] = 1.0f; flagS[128 + tid] = 1.0f;
        refsS[tid] = 0.0f; refsS[128 + tid] = 0.0f;
        eD01[2 * tid]     = __expf(D[tid * NS + 0]);
        eD01[2 * tid + 1] = __expf(D[tid * NS + 1]);
    }
    if (tid < 8) wred[tid] = 0.0f;
    if (tid < 2) eflg[tid] = -7;

    // ---------- role setup ----------
    float alpha = 0.f, cum = 0.f, ref = 0.f, v_prev = 0.f, fpend = 1.f, Mprev = 0.f;
    float lb_cur = 0.f, pij = 0.f;
    const float* lbp = logB + (size_t)b * NT * NS + j;
    if (tid < 128) { lb_cur = lbp[0]; pij = pi[j]; }

    u64 wt2[16], q2[16];
    int s = 0;
    if (tid >= 128) {
        s = (tid - 128) >> 7;                       // duration slice 0..3
        #pragma unroll
        for (int k = 0; k < 16; ++k) {
            int cA = 2 + 32 * s + k;                // tap d-1 = 2+32s+k
            int cB = cA + 16;
            float wa = (cA < 128) ? __expf(D[j * NS + cA]) : 0.0f;
            float wb = (cB < 128) ? __expf(D[j * NS + cB]) : 0.0f;
            wt2[k] = pk2(wa, wb);
            q2[k]  = 0ull;
        }
    }
    __syncthreads();

    const u64 Z = 0ull;
    for (int t = 0; t < NT; ++t) {
        if (tid < 128) {
            // ================= g0: full matvec + combine, one thread per state =================
            float4 pd4 = *(const float4*)(pdur + (t & 1) * 512 + 4 * j);
            float2 e01 = *(const float2*)(eD01 + 2 * j);
            float4 wr4 = *(const float4*)(wred + (t & 1) * 4);   // warp maxes of alpha_{t-1}

            float v;
            if (t == 0) {
                v = __expf(pij);
            } else {
                const float* eAj = sm + OFF_EA + (j << 7);
                const float* psc = p_sh + (t & 1) * 128;
                const unsigned sw = (unsigned)(j & 31);
                u64 a0 = Z, a1 = Z, a2 = Z, a3 = Z;
                #pragma unroll 8
                for (int c = 0; c < 32; ++c) {
                    ulonglong2 ev = *(const ulonglong2*)(eAj + (((unsigned)c ^ sw) << 2));
                    ulonglong2 pv = *(const ulonglong2*)(psc + (c << 2));
                    if (c & 1) { a2 = ffma2(pv.x, ev.x, a2); a3 = ffma2(pv.y, ev.y, a3); }
                    else       { a0 = ffma2(pv.x, ev.x, a0); a1 = ffma2(pv.y, ev.y, a1); }
                }
                float x0, x1, y0, y1, z0, z1, u0, u1;
                upk2(a0, x0, x1); upk2(a1, y0, y1); upk2(a2, z0, z1); upk2(a3, u0, u1);
                float S = ((x0 + x1) + (y0 + y1)) + ((z0 + z1) + (u0 + u1));
                v = S * __expf(Mprev - cum - ref);  // exp(entry_t - cum_t - ref)
            }
            float tail = (pd4.x + pd4.y) + (pd4.z + pd4.w);
            float dot = fmaf(fpend, tail, fmaf(e01.y, v_prev, e01.x * v));

            cum += lb_cur;                          // cum[t+1]
            alpha = cum + ref + __logf(dot);
            lb_cur = (t + 1 < NT) ? lbp[(size_t)(t + 1) * NS] : 0.0f;

            bool sched = ((t & 15) == 15);
            bool emerg = (v > 1e13f);
            float ins, fac;
            if (emerg | (sched & (v > 1e-35f))) {
                float lv = __logf(v);
                ref += lv; ins = 1.0f; fac = __expf(-lv);
                if (emerg & !sched) eflg[t & 1] = t;   // benign same-value race
            } else { ins = v; fac = 1.0f; }
            fpend = fac; v_prev = ins;
            flagS[(t & 1) * 128 + j] = fac;
            refsS[(t & 1) * 128 + j] = ref;
            const int sl = t & 127;
            ring_v[sl * NS + j] = ins;
            ring_r[sl * NS + j] = ref;

            float Mnow = fmaxf(fmaxf(wr4.x, wr4.y), fmaxf(wr4.z, wr4.w));
            p_sh[((t + 1) & 1) * 128 + j] = __expf(alpha - Mnow);
            Mprev = Mnow;

            unsigned ku = f2key(alpha), r;
            asm volatile("redux.sync.max.u32 %0, %1, 0xffffffff;" : "=r"(r) : "r"(ku));
            if (lane == 0) wred[((t + 1) & 1) * 4 + w] = key2f(r);
        } else {
            // ================= dur: 32-tap sliding window in registers =================
            if (t > 0) {
                bool rs = ((((t - 1) & 15) == 15) || (eflg[(t - 1) & 1] == t - 1));
                if (rs) {
                    float fac = flagS[((t - 1) & 1) * 128 + j];
                    u64 fac2 = pk2(fac, fac);
                    #pragma unroll
                    for (int k = 0; k < 16; ++k) q2[k] = fmul2(q2[k], fac2);
                }
            }
            const int bslot = (t - 1 - 32 * s) & 127;     // v_{t-1-32s}  (fixed off-by-one)
            float bv = ring_v[bslot * NS + j];
            float br = ring_r[bslot * NS + j];
            float rn = refsS[((t - 1) & 1) * 128 + j];
            float nv = __expf(fminf(__logf(bv) + (br - rn), 85.0f));
            float lo15 = lo2(q2[15]);
            #pragma unroll
            for (int k = 15; k >= 1; --k) q2[k] = q2[k - 1];
            q2[0] = pk2(nv, lo15);

            u64 a0 = Z, a1 = Z, a2 = Z, a3 = Z;
            #pragma unroll
            for (int k = 0; k < 16; k += 4) {
                a0 = ffma2(q2[k + 0], wt2[k + 0], a0);
                a1 = ffma2(q2[k + 1], wt2[k + 1], a1);
                a2 = ffma2(q2[k + 2], wt2[k + 2], a2);
                a3 = ffma2(q2[k + 3], wt2[k + 3], a3);
            }
            float x0, x1, y0, y1, z0, z1, u0, u1;
            upk2(a0, x0, x1); upk2(a1, y0, y1); upk2(a2, z0, z1); upk2(a3, u0, u1);
            pdur[((t + 1) & 1) * 512 + 4 * j + s] =
                ((x0 + x1) + (y0 + y1)) + ((z0 + z1) + (u0 + u1));
        }
        __syncthreads();   // loop carry
    }

    // ---------- loglik[b] = LSE_j alpha[T-1, j] ----------
    if (tid < 128) {
        float mv = alpha;
        #pragma unroll
        for (int o = 16; o > 0; o >>= 1)
            mv = fmaxf(mv, __shfl_xor_sync(0xffffffffu, mv, o));
        if (lane == 0) fin[w] = mv;
    }
    __syncthreads();
    float m = fmaxf(fmaxf(fin[0], fin[1]), fmaxf(fin[2], fin[3]));
    if (tid < 128) {
        float e = __expf(alpha - m);
        #pragma unroll
        for (int o = 16; o > 0; o >>= 1)
            e += __shfl_xor_sync(0xffffffffu, e, o);
        if (lane == 0) fin[8 + w] = e;
    }
    __syncthreads();
    if (tid == 0) {
        float ssum = (fin[8] + fin[9]) + (fin[10] + fin[11]);
        out[b] = m + __logf(ssum);
    }
}

extern "C" void kernel_launch(void* const* d_in, const int* in_sizes, int n_in,
                              void* d_out, int out_size)
{
    const float* logB = (const float*)d_in[0];
    const float* pi   = (const float*)d_in[1];
    const float* A    = (const float*)d_in[2];
    const float* D    = (const float*)d_in[3];
    float* out = (float*)d_out;

    const size_t smem_bytes = (size_t)SMEM_FLOATS * sizeof(float);  // ~200.1 KB
    cudaFuncSetAttribute(hsmm_fwd_kernel,
                         cudaFuncAttributeMaxDynamicSharedMemorySize,
                         (int)smem_bytes);
    hsmm_fwd_kernel<<<NB, NTHR, smem_bytes>>>(logB, pi, A, D, out);
}

// round 9
// speedup vs baseline: 1.2049x; 1.2037x over previous
#include <cuda_runtime.h>

#define NS   128
#define NT   2048
#define NB   64
#define NTHR 512   // 4 slices (s=tid>>7) x 128 states; every thread: matvec + dur; tid<128 also combine

// float-index offsets in dynamic smem
#define OFF_RING 0       // 32768: u64 ring[128 slots][128 j] = (v_ins, ref_ins)
#define OFF_PSH  32768   // 256:  [buf][j] exp(alpha - M)
#define OFF_PMAT 33024   // 512:  [s][j] matvec partials
#define OFF_PDUR 33536   // 1024: [buf][s][j] duration tail partials
#define OFF_FLAG 34560   // 256:  [buf][j] rescale factor
#define OFF_REFS 34816   // 256:  [buf][j] ref after that step
#define OFF_ED   35072   // 256:  [j*2+{0,1}] exp(D[j][0..1])
#define OFF_WRED 35328   // 8:    [buf][w] per-warp alpha maxes
#define OFF_EFLG 35336   // 2 ints: emergency-rescale generation, by parity
#define OFF_FIN  35340   // 16
#define SMEM_FLOATS 35360  // ~138.1 KB

typedef unsigned long long u64;

__device__ __forceinline__ u64 pk2(float lo, float hi) {
    u64 r;
    asm("mov.b64 %0, {%1, %2};" : "=l"(r)
        : "r"(__float_as_uint(lo)), "r"(__float_as_uint(hi)));
    return r;
}
__device__ __forceinline__ void upk2(u64 v, float& lo, float& hi) {
    unsigned a, b;
    asm("mov.b64 {%0, %1}, %2;" : "=r"(a), "=r"(b) : "l"(v));
    lo = __uint_as_float(a); hi = __uint_as_float(b);
}
__device__ __forceinline__ float lo2(u64 v) { float a, b; upk2(v, a, b); return a; }
__device__ __forceinline__ u64 ffma2(u64 a, u64 b, u64 c) {
    u64 d;
    asm("fma.rn.f32x2 %0, %1, %2, %3;" : "=l"(d) : "l"(a), "l"(b), "l"(c));
    return d;
}
__device__ __forceinline__ u64 fmul2(u64 a, u64 b) {
    u64 d;
    asm("mul.rn.f32x2 %0, %1, %2;" : "=l"(d) : "l"(a), "l"(b));
    return d;
}
__device__ __forceinline__ unsigned f2key(float x) {
    int i = __float_as_int(x);
    return (unsigned)(i ^ ((i >> 31) | 0x80000000));
}
__device__ __forceinline__ float key2f(unsigned k) {
    int i = ((int)k < 0) ? (int)(k ^ 0x80000000u) : (int)(~k);
    return __int_as_float(i);
}

__global__ __launch_bounds__(NTHR, 1)
void hsmm_fwd_kernel(const float* __restrict__ logB,
                     const float* __restrict__ pi,
                     const float* __restrict__ A,
                     const float* __restrict__ D,
                     float* __restrict__ out)
{
    extern __shared__ float sm[];
    u64*   ring64 = (u64*)(sm + OFF_RING);
    float* p_sh   = sm + OFF_PSH;
    float* pmat   = sm + OFF_PMAT;
    float* pdur   = sm + OFF_PDUR;
    float* flagS  = sm + OFF_FLAG;
    float* refsS  = sm + OFF_REFS;
    float* eD01   = sm + OFF_ED;
    float* wred   = sm + OFF_WRED;
    int*   eflg   = (int*)(sm + OFF_EFLG);
    float* fin    = sm + OFF_FIN;

    const int tid  = threadIdx.x;
    const int b    = blockIdx.x;
    const int lane = tid & 31;
    const int w    = tid >> 5;
    const int j    = tid & 127;
    const int s    = tid >> 7;          // slice 0..3

    // ---------- register tables (both roles in every thread) ----------
    u64 awt[16], dwt[16], q2[16];
    #pragma unroll
    for (int m = 0; m < 16; ++m) {
        int i0 = 32 * s + 2 * m;
        awt[m] = pk2(__expf(A[i0 * NS + j]), __expf(A[(i0 + 1) * NS + j]));
        int cA = 2 + 32 * s + m;        // tap d-1 = 2+32s+m
        int cB = cA + 16;
        float wa = (cA < 128) ? __expf(D[j * 128 + cA]) : 0.0f;
        float wb = (cB < 128) ? __expf(D[j * 128 + cB]) : 0.0f;
        dwt[m] = pk2(wa, wb);
        q2[m]  = 0ull;
    }

    // ---------- init smem ----------
    for (int lin = tid; lin < 16384; lin += NTHR) ring64[lin] = 0ull;
    for (int lin = tid; lin < 1024;  lin += NTHR) pdur[lin] = 0.0f;
    if (tid < 128) {
        p_sh[tid] = 0.0f;  p_sh[128 + tid] = 0.0f;
        flagS[tid] = 1.0f; flagS[128 + tid] = 1.0f;
        refsS[tid] = 0.0f; refsS[128 + tid] = 0.0f;
        eD01[2 * tid]     = __expf(D[tid * 128 + 0]);
        eD01[2 * tid + 1] = __expf(D[tid * 128 + 1]);
    }
    if (tid < 8) wred[tid] = 0.0f;
    if (tid < 2) eflg[tid] = -7;

    // combine-role scalars (tid<128)
    float alpha = 0.f, cum = 0.f, ref = 0.f, v_prev = 0.f, fpend = 1.f, Mprev = 0.f;
    float lb_cur = 0.f, pij = 0.f;
    const float* lbp = logB + (size_t)b * NT * NS + j;
    if (tid < 128) { lb_cur = lbp[0]; pij = pi[j]; }
    __syncthreads();

    const u64 Z = 0ull;
    for (int t = 0; t < NT; ++t) {
        // ================= Phase A: trans matvec partial (all threads) =================
        if (t > 0) {
            const float* psc = p_sh + (t & 1) * 128 + 32 * s;
            u64 a0 = Z, a1 = Z, a2 = Z, a3 = Z;
            #pragma unroll
            for (int k = 0; k < 8; ++k) {
                ulonglong2 pv = *(const ulonglong2*)(psc + 4 * k);   // broadcast
                if (k & 1) { a2 = ffma2(pv.x, awt[2 * k], a2); a3 = ffma2(pv.y, awt[2 * k + 1], a3); }
                else       { a0 = ffma2(pv.x, awt[2 * k], a0); a1 = ffma2(pv.y, awt[2 * k + 1], a1); }
            }
            float x0, x1, y0, y1, z0, z1, u0, u1;
            upk2(a0, x0, x1); upk2(a1, y0, y1); upk2(a2, z0, z1); upk2(a3, u0, u1);
            pmat[s * 128 + j] = ((x0 + x1) + (y0 + y1)) + ((z0 + z1) + (u0 + u1));
        }
        __syncthreads();                                   // sync1: pmat ready

        // ================= Phase B ==================================================
        if (tid < 128) {
            // ---- combine: one thread per state (one warp per SMSP) ----
            float2 e01 = *(const float2*)(eD01 + 2 * j);
            float4 wr4 = *(const float4*)(wred + (t & 1) * 4);
            float tl0 = pdur[(t & 1) * 512 +   0 + j];
            float tl1 = pdur[(t & 1) * 512 + 128 + j];
            float tl2 = pdur[(t & 1) * 512 + 256 + j];
            float tl3 = pdur[(t & 1) * 512 + 384 + j];
            float v;
            if (t == 0) {
                v = __expf(pij);
            } else {
                float S = (pmat[j] + pmat[128 + j]) + (pmat[256 + j] + pmat[384 + j]);
                v = S * __expf(Mprev - cum - ref);        // exp(entry_t - cum_t - ref)
            }
            float tail = (tl0 + tl1) + (tl2 + tl3);
            float dot = fmaf(fpend, tail, fmaf(e01.y, v_prev, e01.x * v));

            cum += lb_cur;                                // cum[t+1]
            alpha = cum + ref + __logf(dot);
            lb_cur = (t + 1 < NT) ? lbp[(size_t)(t + 1) * NS] : 0.0f;

            bool sched = ((t & 15) == 15);
            bool emerg = (v > 1e13f);
            float ins, fac;
            if (emerg | (sched & (v > 1e-35f))) {
                float lv = __logf(v);
                ref += lv; ins = 1.0f; fac = __expf(-lv);
                if (emerg & !sched) eflg[t & 1] = t;      // benign same-value race
            } else { ins = v; fac = 1.0f; }
            fpend = fac; v_prev = ins;
            flagS[(t & 1) * 128 + j] = fac;
            refsS[(t & 1) * 128 + j] = ref;
            ring64[(t & 127) * 128 + j] = pk2(ins, ref);

            float Mnow = fmaxf(fmaxf(wr4.x, wr4.y), fmaxf(wr4.z, wr4.w));
            p_sh[((t + 1) & 1) * 128 + j] = __expf(alpha - Mnow);
            Mprev = Mnow;

            unsigned ku = f2key(alpha), r;
            asm volatile("redux.sync.max.u32 %0, %1, 0xffffffff;" : "=r"(r) : "r"(ku));
            if (lane == 0) wred[((t + 1) & 1) * 4 + w] = key2f(r);
        }

        // ---- dur: 32-tap sliding window in registers (all threads) ----
        {
            if (t > 0) {
                bool rs = ((((t - 1) & 15) == 15) || (eflg[(t - 1) & 1] == t - 1));
                if (rs) {
                    float fac = flagS[((t - 1) & 1) * 128 + j];
                    u64 fac2 = pk2(fac, fac);
                    #pragma unroll
                    for (int k = 0; k < 16; ++k) q2[k] = fmul2(q2[k], fac2);
                }
            }
            const int bslot = (t - 1 - 32 * s) & 127;     // v_{t-1-32s}
            float bv, br;
            upk2(ring64[bslot * 128 + j], bv, br);
            float rn = refsS[((t - 1) & 1) * 128 + j];
            float nv = (br == rn) ? bv
                     : __expf(fminf(__logf(bv) + (br - rn), 85.0f));
            float lo15 = lo2(q2[15]);
            #pragma unroll
            for (int k = 15; k >= 1; --k) q2[k] = q2[k - 1];
            q2[0] = pk2(nv, lo15);

            u64 a0 = Z, a1 = Z, a2 = Z, a3 = Z;
            #pragma unroll
            for (int k = 0; k < 16; k += 4) {
                a0 = ffma2(q2[k + 0], dwt[k + 0], a0);
                a1 = ffma2(q2[k + 1], dwt[k + 1], a1);
                a2 = ffma2(q2[k + 2], dwt[k + 2], a2);
                a3 = ffma2(q2[k + 3], dwt[k + 3], a3);
            }
            float x0, x1, y0, y1, z0, z1, u0, u1;
            upk2(a0, x0, x1); upk2(a1, y0, y1); upk2(a2, z0, z1); upk2(a3, u0, u1);
            pdur[((t + 1) & 1) * 512 + s * 128 + j] =
                ((x0 + x1) + (y0 + y1)) + ((z0 + z1) + (u0 + u1));
        }
        __syncthreads();                                   // sync2: loop carry
    }

    // ---------- loglik[b] = LSE_j alpha[T-1, j] ----------
    if (tid < 128) {
        float mv = alpha;
        #pragma unroll
        for (int o = 16; o > 0; o >>= 1)
            mv = fmaxf(mv, __shfl_xor_sync(0xffffffffu, mv, o));
        if (lane == 0) fin[w] = mv;
    }
    __syncthreads();
    float m = fmaxf(fmaxf(fin[0], fin[1]), fmaxf(fin[2], fin[3]));
    if (tid < 128) {
        float e = __expf(alpha - m);
        #pragma unroll
        for (int o = 16; o > 0; o >>= 1)
            e += __shfl_xor_sync(0xffffffffu, e, o);
        if (lane == 0) fin[8 + w] = e;
    }
    __syncthreads();
    if (tid == 0) {
        float ssum = (fin[8] + fin[9]) + (fin[10] + fin[11]);
        out[b] = m + __logf(ssum);
    }
}

extern "C" void kernel_launch(void* const* d_in, const int* in_sizes, int n_in,
                              void* d_out, int out_size)
{
    const float* logB = (const float*)d_in[0];
    const float* pi   = (const float*)d_in[1];
    const float* A    = (const float*)d_in[2];
    const float* D    = (const float*)d_in[3];
    float* out = (float*)d_out;

    const size_t smem_bytes = (size_t)SMEM_FLOATS * sizeof(float);  // ~138.1 KB
    cudaFuncSetAttribute(hsmm_fwd_kernel,
                         cudaFuncAttributeMaxDynamicSharedMemorySize,
                         (int)smem_bytes);
    hsmm_fwd_kernel<<<NB, NTHR, smem_bytes>>>(logB, pi, A, D, out);
}

// round 10
// speedup vs baseline: 2.8414x; 2.3581x over previous
#include <cuda_runtime.h>

#define NS   128
#define NT   2048
#define NB   64
#define NTHR 512   // 4 slices (s=tid>>7) x 128 states; every thread: matvec + dur; tid<128 also combine

// float-index offsets in dynamic smem (identical to R9)
#define OFF_RING 0       // 32768: u64 ring[128 slots][128 j] = (v_ins, ref_ins)
#define OFF_PSH  32768   // 256:  [buf][j] exp(alpha - M)
#define OFF_PMAT 33024   // 512:  [s][j] matvec partials
#define OFF_PDUR 33536   // 1024: [buf][s][j] duration tail partials
#define OFF_FLAG 34560   // 256:  [buf][j] rescale factor
#define OFF_REFS 34816   // 256:  [buf][j] ref after that step
#define OFF_ED   35072   // 256:  [j*2+{0,1}] exp(D[j][0..1])
#define OFF_WRED 35328   // 8:    [buf][w] per-warp alpha maxes
#define OFF_EFLG 35336   // 2 ints: emergency-rescale generation, by parity
#define OFF_FIN  35340   // 16
#define SMEM_FLOATS 35360  // ~138.1 KB

typedef unsigned long long u64;

__device__ __forceinline__ u64 pk2(float lo, float hi) {
    u64 r;
    asm("mov.b64 %0, {%1, %2};" : "=l"(r)
        : "r"(__float_as_uint(lo)), "r"(__float_as_uint(hi)));
    return r;
}
__device__ __forceinline__ void upk2(u64 v, float& lo, float& hi) {
    unsigned a, b;
    asm("mov.b64 {%0, %1}, %2;" : "=r"(a), "=r"(b) : "l"(v));
    lo = __uint_as_float(a); hi = __uint_as_float(b);
}
__device__ __forceinline__ u64 ffma2(u64 a, u64 b, u64 c) {
    u64 d;
    asm("fma.rn.f32x2 %0, %1, %2, %3;" : "=l"(d) : "l"(a), "l"(b), "l"(c));
    return d;
}
__device__ __forceinline__ unsigned f2key(float x) {
    int i = __float_as_int(x);
    return (unsigned)(i ^ ((i >> 31) | 0x80000000));
}
__device__ __forceinline__ float key2f(unsigned k) {
    int i = ((int)k < 0) ? (int)(k ^ 0x80000000u) : (int)(~k);
    return __int_as_float(i);
}

__global__ __launch_bounds__(NTHR, 1)
void hsmm_fwd_kernel(const float* __restrict__ logB,
                     const float* __restrict__ pi,
                     const float* __restrict__ A,
                     const float* __restrict__ D,
                     float* __restrict__ out)
{
    extern __shared__ float sm[];
    u64*   ring64 = (u64*)(sm + OFF_RING);
    float* p_sh   = sm + OFF_PSH;
    float* pmat   = sm + OFF_PMAT;
    float* pdur   = sm + OFF_PDUR;
    float* flagS  = sm + OFF_FLAG;
    float* refsS  = sm + OFF_REFS;
    float* eD01   = sm + OFF_ED;
    float* wred   = sm + OFF_WRED;
    int*   eflg   = (int*)(sm + OFF_EFLG);
    float* fin    = sm + OFF_FIN;

    const int tid  = threadIdx.x;
    const int b    = blockIdx.x;
    const int lane = tid & 31;
    const int w    = tid >> 5;
    const int j    = tid & 127;
    const int s    = tid >> 7;          // slice 0..3

    // ---------- register tables ----------
    u64   awt[16];      // packed exp(A) pairs for matvec slice s (32 i's)
    float dwt[32];      // scalar exp(D) taps, d-1 = 2+32s+k
    float q[32];        // circular window: q[tau & 31] = v_tau (slice-shifted stream)
    #pragma unroll
    for (int m = 0; m < 16; ++m) {
        int i0 = 32 * s + 2 * m;
        awt[m] = pk2(__expf(A[i0 * NS + j]), __expf(A[(i0 + 1) * NS + j]));
    }
    #pragma unroll
    for (int k = 0; k < 32; ++k) {
        int c = 2 + 32 * s + k;
        dwt[k] = (c < 128) ? __expf(D[j * 128 + c]) : 0.0f;
        q[k] = 0.0f;
    }

    // ---------- init smem ----------
    for (int lin = tid; lin < 16384; lin += NTHR) ring64[lin] = 0ull;
    for (int lin = tid; lin < 1024;  lin += NTHR) pdur[lin] = 0.0f;
    if (tid < 128) {
        p_sh[tid] = 0.0f;  p_sh[128 + tid] = 0.0f;
        flagS[tid] = 1.0f; flagS[128 + tid] = 1.0f;
        refsS[tid] = 0.0f; refsS[128 + tid] = 0.0f;
        eD01[2 * tid]     = __expf(D[tid * 128 + 0]);
        eD01[2 * tid + 1] = __expf(D[tid * 128 + 1]);
    }
    if (tid < 8) wred[tid] = 0.0f;
    if (tid < 2) eflg[tid] = -7;

    // combine-role scalars (tid<128)
    float alpha = 0.f, cum = 0.f, ref = 0.f, v_prev = 0.f, fpend = 1.f, Mprev = 0.f;
    float lb_cur = 0.f;
    const float* lbp = logB + (size_t)b * NT * NS + j;
    if (tid < 128) lb_cur = lbp[0];
    __syncthreads();

    const u64 Z = 0ull;
    for (int tb = 0; tb < NT / 32; ++tb) {
        #pragma unroll
        for (int p = 0; p < 32; ++p) {
            const int t = (tb << 5) + p;

            // ================= Phase A: trans matvec partial (all threads) =================
            if (t > 0) {
                const float* psc = p_sh + (t & 1) * 128 + 32 * s;
                u64 a0 = Z, a1 = Z, a2 = Z, a3 = Z;
                #pragma unroll
                for (int k = 0; k < 8; ++k) {
                    ulonglong2 pv = *(const ulonglong2*)(psc + 4 * k);   // broadcast
                    if (k & 1) { a2 = ffma2(pv.x, awt[2 * k], a2); a3 = ffma2(pv.y, awt[2 * k + 1], a3); }
                    else       { a0 = ffma2(pv.x, awt[2 * k], a0); a1 = ffma2(pv.y, awt[2 * k + 1], a1); }
                }
                float x0, x1, y0, y1, z0, z1, u0, u1;
                upk2(a0, x0, x1); upk2(a1, y0, y1); upk2(a2, z0, z1); upk2(a3, u0, u1);
                pmat[s * 128 + j] = ((x0 + x1) + (y0 + y1)) + ((z0 + z1) + (u0 + u1));
            }
            __syncthreads();                                   // sync1: pmat ready

            // ================= Phase B ==================================================
            if (tid < 128) {
                // ---- combine: one thread per state ----
                float2 e01 = *(const float2*)(eD01 + 2 * j);
                float4 wr4 = *(const float4*)(wred + (t & 1) * 4);
                float tl0 = pdur[(t & 1) * 512 +   0 + j];
                float tl1 = pdur[(t & 1) * 512 + 128 + j];
                float tl2 = pdur[(t & 1) * 512 + 256 + j];
                float tl3 = pdur[(t & 1) * 512 + 384 + j];
                float v;
                if (t == 0) {
                    v = __expf(pi[j]);
                } else {
                    float S = (pmat[j] + pmat[128 + j]) + (pmat[256 + j] + pmat[384 + j]);
                    v = S * __expf(Mprev - cum - ref);        // exp(entry_t - cum_t - ref)
                }
                float tail = (tl0 + tl1) + (tl2 + tl3);
                float dot = fmaf(fpend, tail, fmaf(e01.y, v_prev, e01.x * v));

                cum += lb_cur;                                // cum[t+1]
                alpha = cum + ref + __logf(dot);
                lb_cur = (t + 1 < NT) ? lbp[(size_t)(t + 1) * NS] : 0.0f;

                bool sched = ((t & 15) == 15);
                bool emerg = (v > 1e13f);
                float ins, fac;
                if (emerg | (sched & (v > 1e-35f))) {
                    float lv = __logf(v);
                    ref += lv; ins = 1.0f; fac = __expf(-lv);
                    if (emerg & !sched) eflg[t & 1] = t;      // benign same-value race
                } else { ins = v; fac = 1.0f; }
                fpend = fac; v_prev = ins;
                flagS[(t & 1) * 128 + j] = fac;
                refsS[(t & 1) * 128 + j] = ref;
                ring64[(t & 127) * 128 + j] = pk2(ins, ref);

                float Mnow = fmaxf(fmaxf(wr4.x, wr4.y), fmaxf(wr4.z, wr4.w));
                p_sh[((t + 1) & 1) * 128 + j] = __expf(alpha - Mnow);
                Mprev = Mnow;

                unsigned ku = f2key(alpha), r;
                asm volatile("redux.sync.max.u32 %0, %1, 0xffffffff;" : "=r"(r) : "r"(ku));
                if (lane == 0) wred[((t + 1) & 1) * 4 + w] = key2f(r);
            }

            // ---- dur: 32-tap static circular window in registers (all threads) ----
            {
                if (t > 0) {
                    bool rs = ((((t - 1) & 15) == 15) || (eflg[(t - 1) & 1] == t - 1));
                    if (rs) {
                        float fac = flagS[((t - 1) & 1) * 128 + j];
                        #pragma unroll
                        for (int k = 0; k < 32; ++k) q[k] *= fac;
                    }
                }
                const int bslot = (t - 1 - 32 * s) & 127;     // v_{t-1-32s}
                float bv, br;
                upk2(ring64[bslot * 128 + j], bv, br);
                float rn = refsS[((t - 1) & 1) * 128 + j];
                float nv = (br == rn) ? bv
                         : __expf(fminf(__logf(bv) + (br - rn), 85.0f));
                q[(p + 31) & 31] = nv;                        // q[(t-1) & 31], static index

                float c0 = 0.f, c1 = 0.f, c2 = 0.f, c3 = 0.f;
                #pragma unroll
                for (int k = 0; k < 32; k += 4) {
                    c0 = fmaf(q[(p + 31 - k) & 31], dwt[k + 0], c0);
                    c1 = fmaf(q[(p + 30 - k) & 31], dwt[k + 1], c1);
                    c2 = fmaf(q[(p + 29 - k) & 31], dwt[k + 2], c2);
                    c3 = fmaf(q[(p + 28 - k) & 31], dwt[k + 3], c3);
                }
                pdur[((t + 1) & 1) * 512 + s * 128 + j] = (c0 + c1) + (c2 + c3);
            }
            __syncthreads();                                   // sync2: loop carry
        }
    }

    // ---------- loglik[b] = LSE_j alpha[T-1, j] ----------
    if (tid < 128) {
        float mv = alpha;
        #pragma unroll
        for (int o = 16; o > 0; o >>= 1)
            mv = fmaxf(mv, __shfl_xor_sync(0xffffffffu, mv, o));
        if (lane == 0) fin[w] = mv;
    }
    __syncthreads();
    float m = fmaxf(fmaxf(fin[0], fin[1]), fmaxf(fin[2], fin[3]));
    if (tid < 128) {
        float e = __expf(alpha - m);
        #pragma unroll
        for (int o = 16; o > 0; o >>= 1)
            e += __shfl_xor_sync(0xffffffffu, e, o);
        if (lane == 0) fin[8 + w] = e;
    }
    __syncthreads();
    if (tid == 0) {
        float ssum = (fin[8] + fin[9]) + (fin[10] + fin[11]);
        out[b] = m + __logf(ssum);
    }
}

extern "C" void kernel_launch(void* const* d_in, const int* in_sizes, int n_in,
                              void* d_out, int out_size)
{
    const float* logB = (const float*)d_in[0];
    const float* pi   = (const float*)d_in[1];
    const float* A    = (const float*)d_in[2];
    const float* D    = (const float*)d_in[3];
    float* out = (float*)d_out;

    const size_t smem_bytes = (size_t)SMEM_FLOATS * sizeof(float);  // ~138.1 KB
    cudaFuncSetAttribute(hsmm_fwd_kernel,
                         cudaFuncAttributeMaxDynamicSharedMemorySize,
                         (int)smem_bytes);
    hsmm_fwd_kernel<<<NB, NTHR, smem_bytes>>>(logB, pi, A, D, out);
}